// round 1
// baseline (speedup 1.0000x reference)
#include <cuda_runtime.h>
#include <cuda_bf16.h>
#include <math.h>

// ---------------------------------------------------------------------------
// VectorQuantizer forward on GB300 (sm_103a)
//   x:        [32768, 256] f32
//   codebook: [4096, 256]  f32
// Outputs (flattened tuple, f32):
//   z_q [32768*256], vq_loss, q_loss, commit_loss, entropy_loss, entropy,
//   indices [32768] (as float)
// ---------------------------------------------------------------------------

#define B_ROWS   32768
#define K_CODES  4096
#define DIM      256
#define ZQ_ELEMS (B_ROWS * DIM)          // 8388608
#define SCAL_OFF ZQ_ELEMS
#define IDX_OFF  (ZQ_ELEMS + 5)

// ------------------------- device scratch (static) -------------------------
__device__ float  g_cbn[K_CODES * DIM];   // normalized codebook (4 MB)
__device__ int    g_idx[B_ROWS];          // argmax indices
__device__ int    g_counts[K_CODES];      // histogram
__device__ double g_partials[256];        // per-block loss partial sums

// ------------------------- f32x2 packed helpers ----------------------------
__device__ __forceinline__ unsigned long long packf2(float lo, float hi) {
    unsigned long long r;
    asm("mov.b64 %0, {%1, %2};" : "=l"(r) : "f"(lo), "f"(hi));
    return r;
}
__device__ __forceinline__ void unpackf2(float& lo, float& hi, unsigned long long v) {
    asm("mov.b64 {%0, %1}, %2;" : "=f"(lo), "=f"(hi) : "l"(v));
}
__device__ __forceinline__ unsigned long long fma2(unsigned long long a,
                                                   unsigned long long b,
                                                   unsigned long long c) {
    unsigned long long d;
    asm("fma.rn.f32x2 %0, %1, %2, %3;" : "=l"(d) : "l"(a), "l"(b), "l"(c));
    return d;
}

// ------------------------- K0: zero stats ----------------------------------
__global__ void vq_zero_stats() {
    int t = blockIdx.x * blockDim.x + threadIdx.x;
    if (t < K_CODES) g_counts[t] = 0;
    if (t < 256)     g_partials[t] = 0.0;
}

// ------------------------- K1: normalize codebook --------------------------
// One block (256 threads) per codebook row. Matches jnp: v / max(||v||, 1e-12)
__global__ void vq_normalize_cb(const float* __restrict__ cb) {
    int row = blockIdx.x;
    int t   = threadIdx.x;
    float v = cb[(size_t)row * DIM + t];
    __shared__ float red[256];
    red[t] = v * v;
    __syncthreads();
    for (int s = 128; s > 0; s >>= 1) {
        if (t < s) red[t] += red[t + s];
        __syncthreads();
    }
    float norm = sqrtf(red[0]);
    float r    = 1.0f / fmaxf(norm, 1e-12f);
    g_cbn[(size_t)row * DIM + t] = v * r;
}

// ------------------------- K2: fp32 GEMM + running argmax ------------------
// BM=128 rows of x per CTA, sweep all 4096 codes in BN=128 tiles, BK=8.
// 256 threads, each owns an 8x8 register tile; math uses packed fma.rn.f32x2.
#define BM 128
#define BN 128
#define BK 8
#define TM 8
#define TN 8

__global__ void __launch_bounds__(256, 2)
vq_argmax_gemm(const float* __restrict__ x) {
    __shared__ __align__(16) float As[BK][BM];
    __shared__ __align__(16) float Bs[BK][BN];
    __shared__ float svals[BM][16];
    __shared__ int   sidxs[BM][16];

    const int tid = threadIdx.x;
    const int tx  = tid & 15;        // 0..15  -> column group
    const int ty  = tid >> 4;        // 0..15  -> row group
    const int m0  = blockIdx.x * BM;

    // gmem tile-load mapping: each thread loads one float4
    const int lrow = tid >> 1;           // 0..127
    const int lcol = (tid & 1) * 4;      // 0 or 4

    float best[TM];
    int   bidx[TM];
#pragma unroll
    for (int i = 0; i < TM; i++) { best[i] = -3.0e38f; bidx[i] = 0; }

    const float* xbase = x + (size_t)(m0 + lrow) * DIM + lcol;

    for (int n0 = 0; n0 < K_CODES; n0 += BN) {
        unsigned long long acc[TM][TN / 2];
#pragma unroll
        for (int i = 0; i < TM; i++)
#pragma unroll
            for (int j = 0; j < TN / 2; j++) acc[i][j] = 0ull;  // (0.f, 0.f)

        const float* bbase = g_cbn + (size_t)(n0 + lrow) * DIM + lcol;

        for (int d0 = 0; d0 < DIM; d0 += BK) {
            float4 av = *(const float4*)(xbase + d0);
            float4 bv = *(const float4*)(bbase + d0);
            __syncthreads();            // previous tile fully consumed
            As[lcol + 0][lrow] = av.x;
            As[lcol + 1][lrow] = av.y;
            As[lcol + 2][lrow] = av.z;
            As[lcol + 3][lrow] = av.w;
            Bs[lcol + 0][lrow] = bv.x;
            Bs[lcol + 1][lrow] = bv.y;
            Bs[lcol + 2][lrow] = bv.z;
            Bs[lcol + 3][lrow] = bv.w;
            __syncthreads();

#pragma unroll
            for (int kk = 0; kk < BK; kk++) {
                float4 ma = *(const float4*)&As[kk][ty * TM];
                float4 mb = *(const float4*)&As[kk][ty * TM + 4];
                float4 na = *(const float4*)&Bs[kk][tx * TN];
                float4 nb = *(const float4*)&Bs[kk][tx * TN + 4];
                unsigned long long bn0 = packf2(na.x, na.y);
                unsigned long long bn1 = packf2(na.z, na.w);
                unsigned long long bn2 = packf2(nb.x, nb.y);
                unsigned long long bn3 = packf2(nb.z, nb.w);
                float mv[TM] = {ma.x, ma.y, ma.z, ma.w, mb.x, mb.y, mb.z, mb.w};
#pragma unroll
                for (int i = 0; i < TM; i++) {
                    unsigned long long am = packf2(mv[i], mv[i]);
                    acc[i][0] = fma2(am, bn0, acc[i][0]);
                    acc[i][1] = fma2(am, bn1, acc[i][1]);
                    acc[i][2] = fma2(am, bn2, acc[i][2]);
                    acc[i][3] = fma2(am, bn3, acc[i][3]);
                }
            }
        }

        // fold this 128-code tile into the running per-row argmax
#pragma unroll
        for (int i = 0; i < TM; i++) {
#pragma unroll
            for (int j = 0; j < TN / 2; j++) {
                float lo, hi;
                unpackf2(lo, hi, acc[i][j]);
                int c = n0 + tx * TN + 2 * j;
                if (lo > best[i]) { best[i] = lo; bidx[i] = c; }
                if (hi > best[i]) { best[i] = hi; bidx[i] = c + 1; }
            }
        }
    }

    // cross-thread reduce: 16 column-group candidates per row
    __syncthreads();
#pragma unroll
    for (int i = 0; i < TM; i++) {
        svals[ty * TM + i][tx] = best[i];
        sidxs[ty * TM + i][tx] = bidx[i];
    }
    __syncthreads();
    if (tid < BM) {
        float bv = svals[tid][0];
        int   bi = sidxs[tid][0];
#pragma unroll
        for (int t2 = 1; t2 < 16; t2++) {
            float v = svals[tid][t2];
            int   ix = sidxs[tid][t2];
            if (v > bv || (v == bv && ix < bi)) { bv = v; bi = ix; }
        }
        g_idx[m0 + tid] = bi;
    }
}

// ------------------------- K3: gather + z_q + losses + histogram -----------
// 256 blocks x 256 threads; block handles 128 rows, thread = one dim column.
__global__ void vq_gather_loss(const float* __restrict__ x,
                               const float* __restrict__ cb,
                               float* __restrict__ out) {
    const int m0 = blockIdx.x * 128;
    const int t  = threadIdx.x;
    double lsum = 0.0;
    for (int r = 0; r < 128; r++) {
        int row  = m0 + r;
        int code = g_idx[row];                       // broadcast
        float xv = x[(size_t)row * DIM + t];
        float zv = cb[(size_t)code * DIM + t];
        out[(size_t)row * DIM + t] = xv + (zv - xv); // STE forward == z
        float d = xv - zv;
        lsum += (double)d * (double)d;
        if (t == 0) atomicAdd(&g_counts[code], 1);
    }
    __shared__ double sred[256];
    sred[t] = lsum;
    __syncthreads();
    for (int s = 128; s > 0; s >>= 1) {
        if (t < s) sred[t] += sred[t + s];
        __syncthreads();
    }
    if (t == 0) g_partials[blockIdx.x] = sred[0];
}

// ------------------------- K4: finalize scalars + index tail ---------------
__global__ void vq_finalize(float* __restrict__ out, int out_size) {
    const int t = threadIdx.x;
    __shared__ double sred[256];

    // deterministic sum of 256 loss partials
    sred[t] = g_partials[t];
    __syncthreads();
    for (int s = 128; s > 0; s >>= 1) {
        if (t < s) sred[t] += sred[t + s];
        __syncthreads();
    }
    double q = sred[0] / (double)ZQ_ELEMS;  // q_loss == commit_loss (forward)
    __syncthreads();

    // entropy of codebook usage
    double h = 0.0;
    for (int k = t; k < K_CODES; k += 256) {
        int c = g_counts[k];
        if (c > 0) {
            double p = (double)c / (double)B_ROWS;
            h -= p * log(p);
        }
    }
    sred[t] = h;
    __syncthreads();
    for (int s = 128; s > 0; s >>= 1) {
        if (t < s) sred[t] += sred[t + s];
        __syncthreads();
    }
    double H = sred[0];

    if (t == 0 && out_size >= SCAL_OFF + 5) {
        // vq = q_loss + 0.25*commit + 0.1*(-entropy)
        out[SCAL_OFF + 0] = (float)(1.25 * q - 0.1 * H);
        out[SCAL_OFF + 1] = (float)q;        // q_loss
        out[SCAL_OFF + 2] = (float)q;        // commit_loss
        out[SCAL_OFF + 3] = (float)(-H);     // entropy_loss
        out[SCAL_OFF + 4] = (float)H;        // entropy
    }
    if (out_size >= IDX_OFF + B_ROWS) {
        for (int i = t; i < B_ROWS; i += 256)
            out[IDX_OFF + i] = (float)g_idx[i];
    }
}

// ------------------------- launch ------------------------------------------
extern "C" void kernel_launch(void* const* d_in, const int* in_sizes, int n_in,
                              void* d_out, int out_size) {
    const float* x  = (const float*)d_in[0];
    const float* cb = (const float*)d_in[1];
    // defensive input-order sniff
    if (n_in >= 2 && in_sizes[0] == K_CODES * DIM && in_sizes[1] == B_ROWS * DIM) {
        x  = (const float*)d_in[1];
        cb = (const float*)d_in[0];
    }
    float* out = (float*)d_out;

    vq_zero_stats<<<16, 256>>>();
    vq_normalize_cb<<<K_CODES, 256>>>(cb);
    vq_argmax_gemm<<<B_ROWS / BM, 256>>>(x);
    vq_gather_loss<<<B_ROWS / 128, 256>>>(x, cb, out);
    vq_finalize<<<1, 256>>>(out, out_size);
}

// round 4
// speedup vs baseline: 2.2727x; 2.2727x over previous
#include <cuda_runtime.h>
#include <cuda_bf16.h>
#include <math.h>
#include <cstdint>

// ---------------------------------------------------------------------------
// VectorQuantizer forward on GB300 (sm_103 portable ISA)
//   bf16-split 3-term mma.sync GEMM + exact fp32 rescue for ambiguous rows
// ---------------------------------------------------------------------------

#define B_ROWS   32768
#define K_CODES  4096
#define DIM      256
#define ZQ_ELEMS (B_ROWS * DIM)
#define SCAL_OFF ZQ_ELEMS
#define IDX_OFF  (ZQ_ELEMS + 5)
#define NTILES   32
#define MARGIN   1e-4f
#define MAX_AMBIG 4096

// ------------------------- device scratch (static) -------------------------
__device__ __align__(16) __nv_bfloat16 g_xs[B_ROWS * 512];     // [row][hi256|lo256]
__device__ __align__(16) __nv_bfloat16 g_cbhi[K_CODES * DIM];
__device__ __align__(16) __nv_bfloat16 g_cblo[K_CODES * DIM];
__device__ __align__(16) float g_cbn[K_CODES * DIM];           // normalized fp32
__device__ int    g_idx[B_ROWS];
__device__ int    g_counts[K_CODES];
__device__ double g_partials[1024];
__device__ int    g_ambig_n;
__device__ int    g_ambig[MAX_AMBIG];
__device__ float  g_resc_v[MAX_AMBIG * 64];
__device__ int    g_resc_i[MAX_AMBIG * 64];

// ------------------------- helpers -----------------------------------------
__device__ __forceinline__ uint32_t smem_u32(const void* p) {
    uint32_t a;
    asm("{ .reg .u64 t; cvta.to.shared.u64 t, %1; cvt.u32.u64 %0, t; }"
        : "=r"(a) : "l"(p));
    return a;
}
__device__ __forceinline__ void cp_async16(uint32_t dst, const void* src) {
    asm volatile("cp.async.cg.shared.global [%0], [%1], 16;"
                 :: "r"(dst), "l"(src) : "memory");
}
#define CP_COMMIT() asm volatile("cp.async.commit_group;" ::: "memory")

__device__ __forceinline__ void ldm_x4(uint32_t& r0, uint32_t& r1,
                                       uint32_t& r2, uint32_t& r3, uint32_t addr) {
    asm volatile("ldmatrix.sync.aligned.m8n8.x4.shared.b16 {%0,%1,%2,%3}, [%4];"
                 : "=r"(r0), "=r"(r1), "=r"(r2), "=r"(r3) : "r"(addr));
}
__device__ __forceinline__ void mma16816(float* d, const uint32_t* a,
                                         uint32_t b0, uint32_t b1) {
    asm volatile("mma.sync.aligned.m16n8k16.row.col.f32.bf16.bf16.f32 "
                 "{%0,%1,%2,%3}, {%4,%5,%6,%7}, {%8,%9}, {%0,%1,%2,%3};"
                 : "+f"(d[0]), "+f"(d[1]), "+f"(d[2]), "+f"(d[3])
                 : "r"(a[0]), "r"(a[1]), "r"(a[2]), "r"(a[3]), "r"(b0), "r"(b1));
}
__device__ __forceinline__ bool better(float va, int ia, float vb, int ib) {
    return (va > vb) || (va == vb && ia < ib);
}

// ------------------------- K0: zero stats ----------------------------------
__global__ void vq_zero_stats() {
    int t = blockIdx.x * blockDim.x + threadIdx.x;
    if (t < K_CODES) g_counts[t] = 0;
    if (t < 1024)    g_partials[t] = 0.0;
    if (t == 0)      g_ambig_n = 0;
}

// ------------------------- K1a: split x ------------------------------------
__global__ void vq_prep_x(const float* __restrict__ x) {
    size_t i4 = ((size_t)blockIdx.x * 256 + threadIdx.x) * 4;
    float4 v = *(const float4*)(x + i4);
    int row = (int)(i4 >> 8), d = (int)(i4 & 255);
    __nv_bfloat16 h[4], l[4];
    float vv[4] = {v.x, v.y, v.z, v.w};
#pragma unroll
    for (int k = 0; k < 4; k++) {
        h[k] = __float2bfloat16(vv[k]);
        l[k] = __float2bfloat16(vv[k] - __bfloat162float(h[k]));
    }
    __nv_bfloat16* dh = g_xs + (size_t)row * 512 + d;
    __nv_bfloat16* dl = dh + 256;
    *(__nv_bfloat162*)(dh)     = __nv_bfloat162(h[0], h[1]);
    *(__nv_bfloat162*)(dh + 2) = __nv_bfloat162(h[2], h[3]);
    *(__nv_bfloat162*)(dl)     = __nv_bfloat162(l[0], l[1]);
    *(__nv_bfloat162*)(dl + 2) = __nv_bfloat162(l[2], l[3]);
}

// ------------------------- K1b: normalize + split codebook -----------------
__global__ void vq_prep_cb(const float* __restrict__ cb) {
    int row = blockIdx.x, t = threadIdx.x;
    float v = cb[(size_t)row * DIM + t];
    __shared__ float red[256];
    red[t] = v * v;
    __syncthreads();
    for (int s = 128; s > 0; s >>= 1) {
        if (t < s) red[t] += red[t + s];
        __syncthreads();
    }
    float r = 1.0f / fmaxf(sqrtf(red[0]), 1e-12f);
    float val = v * r;
    __nv_bfloat16 hi = __float2bfloat16(val);
    __nv_bfloat16 lo = __float2bfloat16(val - __bfloat162float(hi));
    g_cbn[(size_t)row * DIM + t]  = val;
    g_cbhi[(size_t)row * DIM + t] = hi;
    g_cblo[(size_t)row * DIM + t] = lo;
}

// ------------------------- K2: HMMA GEMM + running top-2 argmax ------------
// 256 threads = 8 warps (2x4 grid), warp tile 64x32, CTA tile 128 x all codes.
// A (hi|lo) resident in swizzled SMEM (128KB); B double-buffered 16KB chunks.
#define AS_BYTES 131072u
#define BS_BYTES 16384u

__global__ void __launch_bounds__(256, 1) vq_mma_argmax() {
    extern __shared__ __align__(1024) char smem[];
    const uint32_t as_base = smem_u32(smem);
    const uint32_t bs_base = as_base + AS_BYTES;

    const int tid   = threadIdx.x;
    const int lane  = tid & 31;
    const int wid   = tid >> 5;
    const int warpM = wid >> 2;       // 0..1
    const int warpN = wid & 3;        // 0..3
    const int m0    = blockIdx.x * 128;

    // ---- A load: 8192 16B units, swizzled ----
    for (int u = tid; u < 8192; u += 256) {
        int row = u >> 6, c16 = u & 63;
        uint32_t dst = as_base + row * 1024 + ((c16 ^ (row & 7)) << 4);
        cp_async16(dst, (const char*)g_xs + ((size_t)(m0 + row) * 512 + c16 * 8) * 2);
    }
    CP_COMMIT();

    // ---- B chunk loader ----
    auto loadB = [&](uint32_t bufb, const __nv_bfloat16* arr, int nt, int c) {
        const char* srcbase = (const char*)arr + (size_t)nt * 65536 + c * 128;
#pragma unroll
        for (int i = 0; i < 4; i++) {
            int u = tid + i * 256;
            int row = u >> 3, c16 = u & 7;
            uint32_t dst = bufb + row * 128 + ((c16 ^ (row & 7)) << 4);
            cp_async16(dst, srcbase + row * 512 + c16 * 16);
        }
        CP_COMMIT();
    };

    // prefetch chunk 0 (nt=0, chi c=0)
    loadB(bs_base, g_cbhi, 0, 0);

    // ---- per-thread ldmatrix address components ----
    uint32_t aoff[4]; int asw[4];
#pragma unroll
    for (int mf = 0; mf < 4; mf++) {
        int arow = warpM * 64 + mf * 16 + (lane & 15);
        aoff[mf] = as_base + arow * 1024;
        asw[mf]  = arow & 7;
    }
    const int ahalf = (lane >> 4) & 1;
    uint32_t boff[2]; int bsw[2];
#pragma unroll
    for (int p = 0; p < 2; p++) {
        int code = warpN * 32 + p * 16 + ((lane >> 4) & 1) * 8 + (lane & 7);
        boff[p] = code * 128;
        bsw[p]  = code & 7;
    }
    const int bku = (lane >> 3) & 1;

    float acc[4][4][4];
#pragma unroll
    for (int i = 0; i < 4; i++)
#pragma unroll
        for (int j = 0; j < 4; j++)
#pragma unroll
            for (int k = 0; k < 4; k++) acc[i][j][k] = 0.0f;

    float v1[8], v2[8];
    int   i1[8];
#pragma unroll
    for (int s = 0; s < 8; s++) { v1[s] = -3.0e38f; v2[s] = -3.0e38f; i1[s] = 0; }

    for (int j = 0; j < 8 * NTILES; j++) {
        const int nt = j >> 3, sub = j & 7;
        // issue next chunk load into opposite buffer
        if (j + 1 < 8 * NTILES) {
            int nt2 = (j + 1) >> 3, sub2 = (j + 1) & 7;
            loadB(bs_base + ((j + 1) & 1) * BS_BYTES,
                  sub2 < 4 ? g_cbhi : g_cblo, nt2, sub2 & 3);
            asm volatile("cp.async.wait_group 1;" ::: "memory");
        } else {
            asm volatile("cp.async.wait_group 0;" ::: "memory");
        }
        __syncthreads();

        const uint32_t buf = bs_base + (j & 1) * BS_BYTES;
        const bool chi = sub < 4;
        const int  c   = sub & 3;
#pragma unroll
        for (int k16 = 0; k16 < 4; k16++) {
            const int kk = k16 * 16;
            // B fragments: 2 x ldmatrix.x4 -> 4 n8 groups
            uint32_t b[4][2];
#pragma unroll
            for (int p = 0; p < 2; p++) {
                uint32_t addr = buf + boff[p] + ((((kk >> 3) + bku) ^ bsw[p]) << 4);
                ldm_x4(b[2 * p][0], b[2 * p][1], b[2 * p + 1][0], b[2 * p + 1][1], addr);
            }
            // term: xhi
            {
                const int kabs = c * 64 + kk;
                uint32_t a[4][4];
#pragma unroll
                for (int mf = 0; mf < 4; mf++) {
                    uint32_t addr = aoff[mf] + ((((kabs >> 3) + ahalf) ^ asw[mf]) << 4);
                    ldm_x4(a[mf][0], a[mf][1], a[mf][2], a[mf][3], addr);
                }
#pragma unroll
                for (int mf = 0; mf < 4; mf++)
#pragma unroll
                    for (int nf = 0; nf < 4; nf++)
                        mma16816(acc[mf][nf], a[mf], b[nf][0], b[nf][1]);
            }
            if (chi) {  // term: xlo x chi
                const int kabs = 256 + c * 64 + kk;
                uint32_t a[4][4];
#pragma unroll
                for (int mf = 0; mf < 4; mf++) {
                    uint32_t addr = aoff[mf] + ((((kabs >> 3) + ahalf) ^ asw[mf]) << 4);
                    ldm_x4(a[mf][0], a[mf][1], a[mf][2], a[mf][3], addr);
                }
#pragma unroll
                for (int mf = 0; mf < 4; mf++)
#pragma unroll
                    for (int nf = 0; nf < 4; nf++)
                        mma16816(acc[mf][nf], a[mf], b[nf][0], b[nf][1]);
            }
        }
        __syncthreads();

        if (sub == 7) {
            // fold this n-tile into running per-thread top-2
#pragma unroll
            for (int mf = 0; mf < 4; mf++)
#pragma unroll
                for (int h = 0; h < 2; h++) {
                    const int s = mf * 2 + h;
#pragma unroll
                    for (int nf = 0; nf < 4; nf++) {
                        int cb0 = nt * 128 + warpN * 32 + nf * 8 + (lane & 3) * 2;
                        float va = acc[mf][nf][2 * h], vb = acc[mf][nf][2 * h + 1];
                        if (va > v1[s]) { v2[s] = v1[s]; v1[s] = va; i1[s] = cb0; }
                        else if (va > v2[s]) v2[s] = va;
                        if (vb > v1[s]) { v2[s] = v1[s]; v1[s] = vb; i1[s] = cb0 + 1; }
                        else if (vb > v2[s]) v2[s] = vb;
                    }
                }
#pragma unroll
            for (int i = 0; i < 4; i++)
#pragma unroll
                for (int jj = 0; jj < 4; jj++)
#pragma unroll
                    for (int k = 0; k < 4; k++) acc[i][jj][k] = 0.0f;
        }
    }

    // ---- final reduce: quad shuffle, then cross-warpN via smem ----
#pragma unroll
    for (int m = 1; m <= 2; m <<= 1) {
#pragma unroll
        for (int s = 0; s < 8; s++) {
            float ov1 = __shfl_xor_sync(0xFFFFFFFFu, v1[s], m);
            int   oi1 = __shfl_xor_sync(0xFFFFFFFFu, i1[s], m);
            float ov2 = __shfl_xor_sync(0xFFFFFFFFu, v2[s], m);
            if (better(ov1, oi1, v1[s], i1[s])) {
                v2[s] = fmaxf(v1[s], ov2); v1[s] = ov1; i1[s] = oi1;
            } else {
                v2[s] = fmaxf(v2[s], ov1);
            }
        }
    }
    float* rv1 = (float*)(smem + AS_BYTES);          // [128][4]
    int*   ri1 = (int*)(smem + AS_BYTES + 2048);
    float* rv2 = (float*)(smem + AS_BYTES + 4096);
    if ((lane & 3) == 0) {
#pragma unroll
        for (int mf = 0; mf < 4; mf++)
#pragma unroll
            for (int h = 0; h < 2; h++) {
                int s = mf * 2 + h;
                int rl = warpM * 64 + mf * 16 + h * 8 + (lane >> 2);
                rv1[rl * 4 + warpN] = v1[s];
                ri1[rl * 4 + warpN] = i1[s];
                rv2[rl * 4 + warpN] = v2[s];
            }
    }
    __syncthreads();
    if (tid < 128) {
        float fv1 = rv1[tid * 4], fv2 = rv2[tid * 4];
        int   fi1 = ri1[tid * 4];
#pragma unroll
        for (int cI = 1; cI < 4; cI++) {
            float ov1 = rv1[tid * 4 + cI], ov2 = rv2[tid * 4 + cI];
            int   oi1 = ri1[tid * 4 + cI];
            if (better(ov1, oi1, fv1, fi1)) {
                fv2 = fmaxf(fv1, ov2); fv1 = ov1; fi1 = oi1;
            } else {
                fv2 = fmaxf(fv2, ov1);
            }
        }
        g_idx[m0 + tid] = fi1;
        if (fv1 - fv2 < MARGIN) {
            int p = atomicAdd(&g_ambig_n, 1);
            if (p < MAX_AMBIG) g_ambig[p] = m0 + tid;
        }
    }
}

// ------------------------- K2b: rescue — exact fp32 slice argmax -----------
// grid 256: block = (slice = bx>>2 of 64 codes) x (row stride bx&3)
__global__ void vq_rescue_partial(const float* __restrict__ x) {
    const int slice = blockIdx.x >> 2;
    const int rmod  = blockIdx.x & 3;
    int n = g_ambig_n; if (n > MAX_AMBIG) n = MAX_AMBIG;
    const int code_l  = threadIdx.x & 63;
    const int quarter = threadIdx.x >> 6;
    const int code    = slice * 64 + code_l;

    __shared__ float xs[256];
    __shared__ float part[4][64];
    __shared__ float swv[2];
    __shared__ int   swi[2];

    for (int fi = rmod; fi < n; fi += 4) {
        int row = g_ambig[fi];
        xs[threadIdx.x] = x[(size_t)row * DIM + threadIdx.x];
        __syncthreads();
        const float* cbr = g_cbn + (size_t)code * DIM + quarter * 64;
        float s = 0.0f;
#pragma unroll 8
        for (int d = 0; d < 64; d++) s = fmaf(xs[quarter * 64 + d], cbr[d], s);
        part[quarter][code_l] = s;
        __syncthreads();
        if (threadIdx.x < 64) {
            float tot = (part[0][code_l] + part[1][code_l]) +
                        (part[2][code_l] + part[3][code_l]);
            float bv = tot; int bi = code;
#pragma unroll
            for (int m = 16; m > 0; m >>= 1) {
                float ov = __shfl_xor_sync(0xFFFFFFFFu, bv, m);
                int   oi = __shfl_xor_sync(0xFFFFFFFFu, bi, m);
                if (better(ov, oi, bv, bi)) { bv = ov; bi = oi; }
            }
            if ((threadIdx.x & 31) == 0) { swv[threadIdx.x >> 5] = bv; swi[threadIdx.x >> 5] = bi; }
        }
        __syncthreads();
        if (threadIdx.x == 0) {
            float bv = swv[0]; int bi = swi[0];
            if (better(swv[1], swi[1], bv, bi)) { bv = swv[1]; bi = swi[1]; }
            g_resc_v[fi * 64 + slice] = bv;
            g_resc_i[fi * 64 + slice] = bi;
        }
        __syncthreads();
    }
}

// ------------------------- K2c: rescue merge -------------------------------
__global__ void vq_rescue_merge() {
    int fi = blockIdx.x * 256 + threadIdx.x;
    int n = g_ambig_n; if (n > MAX_AMBIG) n = MAX_AMBIG;
    if (fi < n) {
        float bv = g_resc_v[fi * 64]; int bi = g_resc_i[fi * 64];
        for (int s = 1; s < 64; s++) {
            float ov = g_resc_v[fi * 64 + s]; int oi = g_resc_i[fi * 64 + s];
            if (better(ov, oi, bv, bi)) { bv = ov; bi = oi; }
        }
        g_idx[g_ambig[fi]] = bi;
    }
}

// ------------------------- K3: gather + z_q + losses + histogram -----------
__global__ void vq_gather_loss(const float* __restrict__ x,
                               const float* __restrict__ cb,
                               float* __restrict__ out) {
    const int m0 = blockIdx.x * 32;
    const int t  = threadIdx.x;
    double lsum = 0.0;
    for (int r = 0; r < 32; r++) {
        int row  = m0 + r;
        int code = g_idx[row];
        float xv = x[(size_t)row * DIM + t];
        float zv = cb[(size_t)code * DIM + t];
        out[(size_t)row * DIM + t] = xv + (zv - xv);
        float d = xv - zv;
        lsum += (double)d * (double)d;
        if (t == 0) atomicAdd(&g_counts[code], 1);
    }
    __shared__ double sred[256];
    sred[t] = lsum;
    __syncthreads();
    for (int s = 128; s > 0; s >>= 1) {
        if (t < s) sred[t] += sred[t + s];
        __syncthreads();
    }
    if (t == 0) g_partials[blockIdx.x] = sred[0];
}

// ------------------------- K4: finalize ------------------------------------
__global__ void vq_finalize(float* __restrict__ out, int out_size) {
    const int t = threadIdx.x;
    __shared__ double sred[256];
    sred[t] = g_partials[t] + g_partials[t + 256] + g_partials[t + 512] + g_partials[t + 768];
    __syncthreads();
    for (int s = 128; s > 0; s >>= 1) {
        if (t < s) sred[t] += sred[t + s];
        __syncthreads();
    }
    double q = sred[0] / (double)ZQ_ELEMS;
    __syncthreads();

    double h = 0.0;
    for (int k = t; k < K_CODES; k += 256) {
        int c = g_counts[k];
        if (c > 0) {
            double p = (double)c / (double)B_ROWS;
            h -= p * log(p);
        }
    }
    sred[t] = h;
    __syncthreads();
    for (int s = 128; s > 0; s >>= 1) {
        if (t < s) sred[t] += sred[t + s];
        __syncthreads();
    }
    double H = sred[0];

    if (t == 0 && out_size >= SCAL_OFF + 5) {
        out[SCAL_OFF + 0] = (float)(1.25 * q - 0.1 * H);
        out[SCAL_OFF + 1] = (float)q;
        out[SCAL_OFF + 2] = (float)q;
        out[SCAL_OFF + 3] = (float)(-H);
        out[SCAL_OFF + 4] = (float)H;
    }
    if (out_size >= IDX_OFF + B_ROWS) {
        for (int i = t; i < B_ROWS; i += 256)
            out[IDX_OFF + i] = (float)g_idx[i];
    }
}

// ------------------------- launch ------------------------------------------
extern "C" void kernel_launch(void* const* d_in, const int* in_sizes, int n_in,
                              void* d_out, int out_size) {
    const float* x  = (const float*)d_in[0];
    const float* cb = (const float*)d_in[1];
    if (n_in >= 2 && in_sizes[0] == K_CODES * DIM && in_sizes[1] == B_ROWS * DIM) {
        x  = (const float*)d_in[1];
        cb = (const float*)d_in[0];
    }
    float* out = (float*)d_out;

    static bool attr_set = false;
    if (!attr_set) {
        cudaFuncSetAttribute(vq_mma_argmax,
                             cudaFuncAttributeMaxDynamicSharedMemorySize,
                             (int)(AS_BYTES + 2 * BS_BYTES));
        attr_set = true;
    }

    vq_zero_stats<<<16, 256>>>();
    vq_prep_x<<<ZQ_ELEMS / 4 / 256, 256>>>(x);
    vq_prep_cb<<<K_CODES, 256>>>(cb);
    vq_mma_argmax<<<B_ROWS / 128, 256, AS_BYTES + 2 * BS_BYTES>>>();
    vq_rescue_partial<<<256, 256>>>(x);
    vq_rescue_merge<<<MAX_AMBIG / 256, 256>>>();
    vq_gather_loss<<<B_ROWS / 32, 256>>>(x, cb, out);
    vq_finalize<<<1, 256>>>(out, out_size);
}

// round 5
// speedup vs baseline: 4.9079x; 2.1594x over previous
#include <cuda_runtime.h>
#include <cuda_bf16.h>
#include <math.h>
#include <cstdint>

// ---------------------------------------------------------------------------
// VectorQuantizer forward (sm_103 portable ISA)
//   1-term bf16 HMMA screening GEMM + margin candidates + exact fp32 rescore
// ---------------------------------------------------------------------------

#define B_ROWS   32768
#define K_CODES  4096
#define DIM      256
#define ZQ_ELEMS (B_ROWS * DIM)
#define SCAL_OFF ZQ_ELEMS
#define IDX_OFF  (ZQ_ELEMS + 5)
#define NTILES   32
#define MARGIN   0.05f
#define MAX_CAND 16
#define MAX_AMBIG 4096

// ------------------------- device scratch (static) -------------------------
__device__ __align__(16) __nv_bfloat16 g_xhi[B_ROWS * DIM];
__device__ __align__(16) __nv_bfloat16 g_cbhi[K_CODES * DIM];
__device__ __align__(16) float g_cbn[K_CODES * DIM];     // normalized fp32
__device__ int    g_idx[B_ROWS];
__device__ int    g_counts[K_CODES];
__device__ double g_partials[1024];
__device__ int    g_ccnt[B_ROWS];
__device__ int    g_cand[B_ROWS * MAX_CAND];
__device__ int    g_ambig_n;
__device__ int    g_ambig[MAX_AMBIG];
__device__ float  g_resc_v[MAX_AMBIG * 64];
__device__ int    g_resc_i[MAX_AMBIG * 64];

// ------------------------- helpers -----------------------------------------
__device__ __forceinline__ uint32_t smem_u32(const void* p) {
    uint32_t a;
    asm("{ .reg .u64 t; cvta.to.shared.u64 t, %1; cvt.u32.u64 %0, t; }"
        : "=r"(a) : "l"(p));
    return a;
}
__device__ __forceinline__ void cp_async16(uint32_t dst, const void* src) {
    asm volatile("cp.async.cg.shared.global [%0], [%1], 16;"
                 :: "r"(dst), "l"(src) : "memory");
}
#define CP_COMMIT() asm volatile("cp.async.commit_group;" ::: "memory")

__device__ __forceinline__ void ldm_x4(uint32_t& r0, uint32_t& r1,
                                       uint32_t& r2, uint32_t& r3, uint32_t addr) {
    asm volatile("ldmatrix.sync.aligned.m8n8.x4.shared.b16 {%0,%1,%2,%3}, [%4];"
                 : "=r"(r0), "=r"(r1), "=r"(r2), "=r"(r3) : "r"(addr));
}
__device__ __forceinline__ void mma16816(float* d, const uint32_t* a,
                                         uint32_t b0, uint32_t b1) {
    asm volatile("mma.sync.aligned.m16n8k16.row.col.f32.bf16.bf16.f32 "
                 "{%0,%1,%2,%3}, {%4,%5,%6,%7}, {%8,%9}, {%0,%1,%2,%3};"
                 : "+f"(d[0]), "+f"(d[1]), "+f"(d[2]), "+f"(d[3])
                 : "r"(a[0]), "r"(a[1]), "r"(a[2]), "r"(a[3]), "r"(b0), "r"(b1));
}
__device__ __forceinline__ bool better(float va, int ia, float vb, int ib) {
    return (va > vb) || (va == vb && ia < ib);
}
// monotone uint encoding of float for atomicMax
__device__ __forceinline__ uint32_t fenc(float f) {
    uint32_t b = __float_as_uint(f);
    return (b & 0x80000000u) ? ~b : (b | 0x80000000u);
}
__device__ __forceinline__ float fdec(uint32_t k) {
    uint32_t b = (k & 0x80000000u) ? (k & 0x7FFFFFFFu) : ~k;
    return __uint_as_float(b);
}

// ------------------------- K0: zero stats ----------------------------------
__global__ void vq_zero_stats() {
    int t = blockIdx.x * blockDim.x + threadIdx.x;
    if (t < K_CODES) g_counts[t] = 0;
    if (t < 1024)    g_partials[t] = 0.0;
    if (t == 0)      g_ambig_n = 0;
}

// ------------------------- K1a: x -> bf16 hi -------------------------------
__global__ void vq_prep_x(const float* __restrict__ x) {
    size_t i4 = ((size_t)blockIdx.x * 256 + threadIdx.x) * 4;
    float4 v = *(const float4*)(x + i4);
    __nv_bfloat16 h0 = __float2bfloat16(v.x), h1 = __float2bfloat16(v.y);
    __nv_bfloat16 h2 = __float2bfloat16(v.z), h3 = __float2bfloat16(v.w);
    *(__nv_bfloat162*)&g_xhi[i4]     = __nv_bfloat162(h0, h1);
    *(__nv_bfloat162*)&g_xhi[i4 + 2] = __nv_bfloat162(h2, h3);
}

// ------------------------- K1b: normalize codebook -------------------------
__global__ void vq_prep_cb(const float* __restrict__ cb) {
    int row = blockIdx.x, t = threadIdx.x;
    float v = cb[(size_t)row * DIM + t];
    __shared__ float red[256];
    red[t] = v * v;
    __syncthreads();
    for (int s = 128; s > 0; s >>= 1) {
        if (t < s) red[t] += red[t + s];
        __syncthreads();
    }
    float r = 1.0f / fmaxf(sqrtf(red[0]), 1e-12f);
    float val = v * r;
    g_cbn[(size_t)row * DIM + t]  = val;
    g_cbhi[(size_t)row * DIM + t] = __float2bfloat16(val);
}

// ------------------------- K2: screening GEMM + candidates -----------------
// CTA = 128 x-rows, 8 warps (2M x 4N), warp tile 64x32, 2 CTAs/SM.
// SMEM: A 64KB (128x256 bf16 swizzled) + B double 2x16KB + cand region.
#define AS_BYTES  65536u
#define BS_BYTES  16384u
#define RM_OFF    98304u      // rowmax[128] uint
#define CNT_OFF   98816u      // cnt[128] int
#define CAND_OFF  99328u      // cand[128][16] int
#define SMEM_TOT  107520u

__global__ void __launch_bounds__(256, 2) vq_mma_argmax() {
    extern __shared__ __align__(1024) char smem[];
    const uint32_t as_base = smem_u32(smem);
    const uint32_t bs_base = as_base + AS_BYTES;
    uint32_t* rowmax = (uint32_t*)(smem + RM_OFF);
    int*      cnt    = (int*)(smem + CNT_OFF);
    int*      cand   = (int*)(smem + CAND_OFF);

    const int tid   = threadIdx.x;
    const int lane  = tid & 31;
    const int wid   = tid >> 5;
    const int warpM = wid >> 2;
    const int warpN = wid & 3;
    const int m0    = blockIdx.x * 128;

    if (tid < 128) { rowmax[tid] = 0u; cnt[tid] = 0; }

    // A load: 4096 16B units
#pragma unroll
    for (int i = 0; i < 16; i++) {
        int u = tid + i * 256;
        int r = u >> 5, c16 = u & 31;
        uint32_t dst = as_base + r * 512 + ((c16 ^ (r & 7)) << 4);
        cp_async16(dst, (const char*)g_xhi + ((size_t)(m0 + r) * DIM + c16 * 8) * 2);
    }
    CP_COMMIT();

    auto loadB = [&](uint32_t bufb, int j) {
        const int nt = j >> 2, c = j & 3;
        const char* srcb = (const char*)g_cbhi +
                           ((size_t)nt * 128 * DIM + c * 64) * 2;
#pragma unroll
        for (int i = 0; i < 4; i++) {
            int u = tid + i * 256;
            int r = u >> 3, c16 = u & 7;
            uint32_t dst = bufb + r * 128 + ((c16 ^ (r & 7)) << 4);
            cp_async16(dst, srcb + (size_t)r * DIM * 2 + c16 * 16);
        }
        CP_COMMIT();
    };
    loadB(bs_base, 0);

    // per-thread ldmatrix address components
    uint32_t aoff[4]; int asw[4];
#pragma unroll
    for (int mf = 0; mf < 4; mf++) {
        int arow = warpM * 64 + mf * 16 + (lane & 15);
        aoff[mf] = as_base + arow * 512;
        asw[mf]  = arow & 7;
    }
    const int ahalf = (lane >> 4) & 1;
    uint32_t boff[2]; int bsw[2];
#pragma unroll
    for (int p = 0; p < 2; p++) {
        int code = warpN * 32 + p * 16 + ((lane >> 4) & 1) * 8 + (lane & 7);
        boff[p] = code * 128;
        bsw[p]  = code & 7;
    }
    const int bku = (lane >> 3) & 1;

    float acc[4][4][4];
#pragma unroll
    for (int i = 0; i < 4; i++)
#pragma unroll
        for (int j = 0; j < 4; j++)
#pragma unroll
            for (int k = 0; k < 4; k++) acc[i][j][k] = 0.0f;

    for (int j = 0; j < 4 * NTILES; j++) {
        if (j + 1 < 4 * NTILES) {
            loadB(bs_base + ((j + 1) & 1) * BS_BYTES, j + 1);
            asm volatile("cp.async.wait_group 1;" ::: "memory");
        } else {
            asm volatile("cp.async.wait_group 0;" ::: "memory");
        }
        __syncthreads();

        const uint32_t buf = bs_base + (j & 1) * BS_BYTES;
        const int c = j & 3;
#pragma unroll
        for (int k16 = 0; k16 < 4; k16++) {
            const int kk = k16 * 16;
            uint32_t b[4][2];
#pragma unroll
            for (int p = 0; p < 2; p++) {
                uint32_t addr = buf + boff[p] + ((((kk >> 3) + bku) ^ bsw[p]) << 4);
                ldm_x4(b[2 * p][0], b[2 * p][1], b[2 * p + 1][0], b[2 * p + 1][1], addr);
            }
            uint32_t a[4][4];
            const int uab = c * 8 + k16 * 2 + ahalf;
#pragma unroll
            for (int mf = 0; mf < 4; mf++) {
                uint32_t addr = aoff[mf] + ((uab ^ asw[mf]) << 4);
                ldm_x4(a[mf][0], a[mf][1], a[mf][2], a[mf][3], addr);
            }
#pragma unroll
            for (int mf = 0; mf < 4; mf++)
#pragma unroll
                for (int nf = 0; nf < 4; nf++)
                    mma16816(acc[mf][nf], a[mf], b[nf][0], b[nf][1]);
        }

        if (c == 3) {
            const int nt = j >> 2;
            // phase 1: fold scores into per-row max
#pragma unroll
            for (int mf = 0; mf < 4; mf++)
#pragma unroll
                for (int h = 0; h < 2; h++) {
                    int r = warpM * 64 + mf * 16 + h * 8 + (lane >> 2);
#pragma unroll
                    for (int nf = 0; nf < 4; nf++) {
                        atomicMax(&rowmax[r], fenc(acc[mf][nf][2 * h]));
                        atomicMax(&rowmax[r], fenc(acc[mf][nf][2 * h + 1]));
                    }
                }
            __syncthreads();
            // phase 2: append candidates within margin of running max
#pragma unroll
            for (int mf = 0; mf < 4; mf++)
#pragma unroll
                for (int h = 0; h < 2; h++) {
                    int r = warpM * 64 + mf * 16 + h * 8 + (lane >> 2);
                    float thr = fdec(rowmax[r]) - MARGIN;
#pragma unroll
                    for (int nf = 0; nf < 4; nf++) {
                        int cb0 = nt * 128 + warpN * 32 + nf * 8 + (lane & 3) * 2;
                        float va = acc[mf][nf][2 * h], vb = acc[mf][nf][2 * h + 1];
                        if (va >= thr) {
                            int p = atomicAdd(&cnt[r], 1);
                            if (p < MAX_CAND) cand[r * MAX_CAND + p] = cb0;
                        }
                        if (vb >= thr) {
                            int p = atomicAdd(&cnt[r], 1);
                            if (p < MAX_CAND) cand[r * MAX_CAND + p] = cb0 + 1;
                        }
                    }
                }
#pragma unroll
            for (int i = 0; i < 4; i++)
#pragma unroll
                for (int jj = 0; jj < 4; jj++)
#pragma unroll
                    for (int k = 0; k < 4; k++) acc[i][jj][k] = 0.0f;
        }
        __syncthreads();
    }

    // flush candidate lists
    if (tid < 128) {
        int row = m0 + tid;
        int c = cnt[tid];
        g_ccnt[row] = c;
        int n = c < MAX_CAND ? c : MAX_CAND;
        for (int i = 0; i < n; i++) g_cand[row * MAX_CAND + i] = cand[tid * MAX_CAND + i];
        if (c > MAX_CAND) {
            int p = atomicAdd(&g_ambig_n, 1);
            if (p < MAX_AMBIG) g_ambig[p] = row;
        }
    }
}

// ------------------------- K2b: exact fp32 rescore of candidates -----------
__global__ void vq_rescore(const float* __restrict__ x) {
    const int lane = threadIdx.x & 31;
    const int wid  = threadIdx.x >> 5;
#pragma unroll
    for (int i = 0; i < 4; i++) {
        int row = (blockIdx.x * 8 + wid) * 4 + i;
        int c = g_ccnt[row];
        if (c > MAX_CAND) continue;           // fallback path owns this row
        float xv[8];
#pragma unroll
        for (int jj = 0; jj < 8; jj++) xv[jj] = x[(size_t)row * DIM + lane + jj * 32];
        float bv = -3.0e38f; int bi = 0x7FFFFFFF;
        for (int k = 0; k < c; k++) {
            int code = g_cand[row * MAX_CAND + k];
            const float* cr = g_cbn + (size_t)code * DIM;
            float s = 0.0f;
#pragma unroll
            for (int jj = 0; jj < 8; jj++) s = fmaf(xv[jj], cr[lane + jj * 32], s);
#pragma unroll
            for (int m = 16; m > 0; m >>= 1) s += __shfl_xor_sync(0xFFFFFFFFu, s, m);
            if (better(s, code, bv, bi)) { bv = s; bi = code; }
        }
        if (lane == 0) g_idx[row] = bi;
    }
}

// ------------------------- K2c/K2d: fallback full scan (overflow rows) -----
__global__ void vq_rescue_partial(const float* __restrict__ x) {
    const int slice = blockIdx.x >> 2;
    const int rmod  = blockIdx.x & 3;
    int n = g_ambig_n; if (n > MAX_AMBIG) n = MAX_AMBIG;
    const int code_l  = threadIdx.x & 63;
    const int quarter = threadIdx.x >> 6;
    const int code    = slice * 64 + code_l;

    __shared__ float xs[256];
    __shared__ float part[4][64];
    __shared__ float swv[2];
    __shared__ int   swi[2];

    for (int fi = rmod; fi < n; fi += 4) {
        int row = g_ambig[fi];
        xs[threadIdx.x] = x[(size_t)row * DIM + threadIdx.x];
        __syncthreads();
        const float* cbr = g_cbn + (size_t)code * DIM + quarter * 64;
        float s = 0.0f;
#pragma unroll 8
        for (int d = 0; d < 64; d++) s = fmaf(xs[quarter * 64 + d], cbr[d], s);
        part[quarter][code_l] = s;
        __syncthreads();
        if (threadIdx.x < 64) {
            float tot = (part[0][code_l] + part[1][code_l]) +
                        (part[2][code_l] + part[3][code_l]);
            float bv = tot; int bi = code;
#pragma unroll
            for (int m = 16; m > 0; m >>= 1) {
                float ov = __shfl_xor_sync(0xFFFFFFFFu, bv, m);
                int   oi = __shfl_xor_sync(0xFFFFFFFFu, bi, m);
                if (better(ov, oi, bv, bi)) { bv = ov; bi = oi; }
            }
            if ((threadIdx.x & 31) == 0) { swv[threadIdx.x >> 5] = bv; swi[threadIdx.x >> 5] = bi; }
        }
        __syncthreads();
        if (threadIdx.x == 0) {
            float bv = swv[0]; int bi = swi[0];
            if (better(swv[1], swi[1], bv, bi)) { bv = swv[1]; bi = swi[1]; }
            g_resc_v[fi * 64 + slice] = bv;
            g_resc_i[fi * 64 + slice] = bi;
        }
        __syncthreads();
    }
}

__global__ void vq_rescue_merge() {
    int fi = blockIdx.x * 256 + threadIdx.x;
    int n = g_ambig_n; if (n > MAX_AMBIG) n = MAX_AMBIG;
    if (fi < n) {
        float bv = g_resc_v[fi * 64]; int bi = g_resc_i[fi * 64];
        for (int s = 1; s < 64; s++) {
            float ov = g_resc_v[fi * 64 + s]; int oi = g_resc_i[fi * 64 + s];
            if (better(ov, oi, bv, bi)) { bv = ov; bi = oi; }
        }
        g_idx[g_ambig[fi]] = bi;
    }
}

// ------------------------- K3: gather + z_q + loss -------------------------
__global__ void vq_gather_loss(const float* __restrict__ x,
                               const float* __restrict__ cb,
                               float* __restrict__ out) {
    const int m0 = blockIdx.x * 64;
    const int t  = threadIdx.x;
    const int col = (t & 63) * 4;
    float facc = 0.0f;
#pragma unroll 4
    for (int it = 0; it < 16; it++) {
        int row = m0 + it * 4 + (t >> 6);
        int code = g_idx[row];
        float4 xv = *(const float4*)(x + (size_t)row * DIM + col);
        float4 cv = *(const float4*)(cb + (size_t)code * DIM + col);
        float4 o;
        o.x = xv.x + (cv.x - xv.x);
        o.y = xv.y + (cv.y - xv.y);
        o.z = xv.z + (cv.z - xv.z);
        o.w = xv.w + (cv.w - xv.w);
        *(float4*)(out + (size_t)row * DIM + col) = o;
        float d0 = xv.x - cv.x, d1 = xv.y - cv.y, d2 = xv.z - cv.z, d3 = xv.w - cv.w;
        facc += d0 * d0 + d1 * d1 + d2 * d2 + d3 * d3;
    }
    __shared__ double sred[256];
    sred[t] = (double)facc;
    __syncthreads();
    for (int s = 128; s > 0; s >>= 1) {
        if (t < s) sred[t] += sred[t + s];
        __syncthreads();
    }
    if (t == 0) g_partials[blockIdx.x] = sred[0];
}

// ------------------------- K3b: histogram ----------------------------------
__global__ void vq_hist() {
    int i = blockIdx.x * 256 + threadIdx.x;
    atomicAdd(&g_counts[g_idx[i]], 1);
}

// ------------------------- K4: finalize ------------------------------------
__global__ void vq_finalize(float* __restrict__ out, int out_size) {
    const int t = threadIdx.x;
    __shared__ double sred[256];
    sred[t] = g_partials[t] + g_partials[t + 256] + g_partials[t + 512] + g_partials[t + 768];
    __syncthreads();
    for (int s = 128; s > 0; s >>= 1) {
        if (t < s) sred[t] += sred[t + s];
        __syncthreads();
    }
    double q = sred[0] / (double)ZQ_ELEMS;
    __syncthreads();

    double h = 0.0;
    for (int k = t; k < K_CODES; k += 256) {
        int c = g_counts[k];
        if (c > 0) {
            double p = (double)c / (double)B_ROWS;
            h -= p * log(p);
        }
    }
    sred[t] = h;
    __syncthreads();
    for (int s = 128; s > 0; s >>= 1) {
        if (t < s) sred[t] += sred[t + s];
        __syncthreads();
    }
    double H = sred[0];

    if (t == 0 && out_size >= SCAL_OFF + 5) {
        out[SCAL_OFF + 0] = (float)(1.25 * q - 0.1 * H);
        out[SCAL_OFF + 1] = (float)q;
        out[SCAL_OFF + 2] = (float)q;
        out[SCAL_OFF + 3] = (float)(-H);
        out[SCAL_OFF + 4] = (float)H;
    }
    if (out_size >= IDX_OFF + B_ROWS) {
        for (int i = t; i < B_ROWS; i += 256)
            out[IDX_OFF + i] = (float)g_idx[i];
    }
}

// ------------------------- launch ------------------------------------------
extern "C" void kernel_launch(void* const* d_in, const int* in_sizes, int n_in,
                              void* d_out, int out_size) {
    const float* x  = (const float*)d_in[0];
    const float* cb = (const float*)d_in[1];
    if (n_in >= 2 && in_sizes[0] == K_CODES * DIM && in_sizes[1] == B_ROWS * DIM) {
        x  = (const float*)d_in[1];
        cb = (const float*)d_in[0];
    }
    float* out = (float*)d_out;

    static bool attr_set = false;
    if (!attr_set) {
        cudaFuncSetAttribute(vq_mma_argmax,
                             cudaFuncAttributeMaxDynamicSharedMemorySize,
                             (int)SMEM_TOT);
        attr_set = true;
    }

    vq_zero_stats<<<16, 256>>>();
    vq_prep_x<<<ZQ_ELEMS / 4 / 256, 256>>>(x);
    vq_prep_cb<<<K_CODES, 256>>>(cb);
    vq_mma_argmax<<<B_ROWS / 128, 256, SMEM_TOT>>>();
    vq_rescore<<<B_ROWS / 32, 256>>>(x);
    vq_rescue_partial<<<256, 256>>>(x);
    vq_rescue_merge<<<MAX_AMBIG / 256, 256>>>();
    vq_gather_loss<<<B_ROWS / 64, 256>>>(x, cb, out);
    vq_hist<<<B_ROWS / 256, 256>>>();
    vq_finalize<<<1, 256>>>(out, out_size);
}

// round 6
// speedup vs baseline: 5.5572x; 1.1323x over previous
#include <cuda_runtime.h>
#include <cuda_bf16.h>
#include <math.h>
#include <cstdint>

// ---------------------------------------------------------------------------
// VectorQuantizer forward (sm_103 portable ISA)
//   1-term bf16 HMMA screening GEMM (64x64 warp tiles) + exact fp32 rescore
// ---------------------------------------------------------------------------

#define B_ROWS   32768
#define K_CODES  4096
#define DIM      256
#define ZQ_ELEMS (B_ROWS * DIM)
#define SCAL_OFF ZQ_ELEMS
#define IDX_OFF  (ZQ_ELEMS + 5)
#define NTILES   32
#define MARGIN   0.05f
#define MAX_CAND 16
#define MAX_AMBIG 4096

// ------------------------- device scratch (static) -------------------------
__device__ __align__(16) __nv_bfloat16 g_xhi[B_ROWS * DIM];
__device__ __align__(16) __nv_bfloat16 g_cbhi[K_CODES * DIM];
__device__ __align__(16) float g_cbn[K_CODES * DIM];     // normalized fp32
__device__ int    g_idx[B_ROWS];
__device__ int    g_counts[K_CODES];
__device__ double g_partials[1024];
__device__ int    g_ccnt[B_ROWS];
__device__ int    g_cand[B_ROWS * MAX_CAND];
__device__ int    g_ambig_n;
__device__ int    g_ambig[MAX_AMBIG];
__device__ float  g_resc_v[MAX_AMBIG * 64];
__device__ int    g_resc_i[MAX_AMBIG * 64];

// ------------------------- helpers -----------------------------------------
__device__ __forceinline__ uint32_t smem_u32(const void* p) {
    uint32_t a;
    asm("{ .reg .u64 t; cvta.to.shared.u64 t, %1; cvt.u32.u64 %0, t; }"
        : "=r"(a) : "l"(p));
    return a;
}
__device__ __forceinline__ void cp_async16(uint32_t dst, const void* src) {
    asm volatile("cp.async.cg.shared.global [%0], [%1], 16;"
                 :: "r"(dst), "l"(src) : "memory");
}
#define CP_COMMIT() asm volatile("cp.async.commit_group;" ::: "memory")

__device__ __forceinline__ void ldm_x4(uint32_t& r0, uint32_t& r1,
                                       uint32_t& r2, uint32_t& r3, uint32_t addr) {
    asm volatile("ldmatrix.sync.aligned.m8n8.x4.shared.b16 {%0,%1,%2,%3}, [%4];"
                 : "=r"(r0), "=r"(r1), "=r"(r2), "=r"(r3) : "r"(addr));
}
__device__ __forceinline__ void mma16816(float* d, const uint32_t* a,
                                         uint32_t b0, uint32_t b1) {
    asm volatile("mma.sync.aligned.m16n8k16.row.col.f32.bf16.bf16.f32 "
                 "{%0,%1,%2,%3}, {%4,%5,%6,%7}, {%8,%9}, {%0,%1,%2,%3};"
                 : "+f"(d[0]), "+f"(d[1]), "+f"(d[2]), "+f"(d[3])
                 : "r"(a[0]), "r"(a[1]), "r"(a[2]), "r"(a[3]), "r"(b0), "r"(b1));
}
__device__ __forceinline__ bool better(float va, int ia, float vb, int ib) {
    return (va > vb) || (va == vb && ia < ib);
}
__device__ __forceinline__ uint32_t fenc(float f) {
    uint32_t b = __float_as_uint(f);
    return (b & 0x80000000u) ? ~b : (b | 0x80000000u);
}
__device__ __forceinline__ float fdec(uint32_t k) {
    uint32_t b = (k & 0x80000000u) ? (k & 0x7FFFFFFFu) : ~k;
    return __uint_as_float(b);
}

// ------------------------- K0: zero stats ----------------------------------
__global__ void vq_zero_stats() {
    int t = blockIdx.x * blockDim.x + threadIdx.x;
    if (t < K_CODES) g_counts[t] = 0;
    if (t < 1024)    g_partials[t] = 0.0;
    if (t == 0)      g_ambig_n = 0;
}

// ------------------------- K1a: x -> bf16 hi -------------------------------
__global__ void vq_prep_x(const float* __restrict__ x) {
    size_t i4 = ((size_t)blockIdx.x * 256 + threadIdx.x) * 4;
    float4 v = *(const float4*)(x + i4);
    __nv_bfloat16 h0 = __float2bfloat16(v.x), h1 = __float2bfloat16(v.y);
    __nv_bfloat16 h2 = __float2bfloat16(v.z), h3 = __float2bfloat16(v.w);
    *(__nv_bfloat162*)&g_xhi[i4]     = __nv_bfloat162(h0, h1);
    *(__nv_bfloat162*)&g_xhi[i4 + 2] = __nv_bfloat162(h2, h3);
}

// ------------------------- K1b: normalize codebook -------------------------
__global__ void vq_prep_cb(const float* __restrict__ cb) {
    int row = blockIdx.x, t = threadIdx.x;
    float v = cb[(size_t)row * DIM + t];
    __shared__ float red[256];
    red[t] = v * v;
    __syncthreads();
    for (int s = 128; s > 0; s >>= 1) {
        if (t < s) red[t] += red[t + s];
        __syncthreads();
    }
    float r = 1.0f / fmaxf(sqrtf(red[0]), 1e-12f);
    float val = v * r;
    g_cbn[(size_t)row * DIM + t]  = val;
    g_cbhi[(size_t)row * DIM + t] = __float2bfloat16(val);
}

// ------------------------- K2: screening GEMM + candidates -----------------
// CTA = 128 x-rows x 128-code tiles, 4 warps in 2x2 grid, warp tile 64x64.
// SMEM: A 64KB + B double 2x16KB + rowmax/cnt/cand. 2 CTAs/SM, 128 thr.
#define AS_BYTES  65536u
#define BS_BYTES  16384u
#define RM_OFF    98304u      // rowmax[128] uint
#define CNT_OFF   98816u      // cnt[128] int
#define CAND_OFF  99328u      // cand[128][16] int
#define SMEM_TOT  107520u

__global__ void __launch_bounds__(128, 2) vq_mma_argmax() {
    extern __shared__ __align__(1024) char smem[];
    const uint32_t as_base = smem_u32(smem);
    const uint32_t bs_base = as_base + AS_BYTES;
    uint32_t* rowmax = (uint32_t*)(smem + RM_OFF);
    int*      cnt    = (int*)(smem + CNT_OFF);
    int*      cand   = (int*)(smem + CAND_OFF);

    const int tid   = threadIdx.x;
    const int lane  = tid & 31;
    const int wid   = tid >> 5;
    const int warpM = wid >> 1;       // 0..1 (64 rows each)
    const int warpN = wid & 1;        // 0..1 (64 codes each)
    const int m0    = blockIdx.x * 128;

    rowmax[tid] = 0u; cnt[tid] = 0;

    // A load: 4096 16B units over 128 threads
#pragma unroll
    for (int i = 0; i < 32; i++) {
        int u = tid + i * 128;
        int r = u >> 5, c16 = u & 31;
        uint32_t dst = as_base + r * 512 + ((c16 ^ (r & 7)) << 4);
        cp_async16(dst, (const char*)g_xhi + ((size_t)(m0 + r) * DIM + c16 * 8) * 2);
    }
    CP_COMMIT();

    auto loadB = [&](uint32_t bufb, int j) {
        const int nt = j >> 2, c = j & 3;
        const char* srcb = (const char*)g_cbhi +
                           ((size_t)nt * 128 * DIM + c * 64) * 2;
#pragma unroll
        for (int i = 0; i < 8; i++) {
            int u = tid + i * 128;
            int r = u >> 3, c16 = u & 7;
            uint32_t dst = bufb + r * 128 + ((c16 ^ (r & 7)) << 4);
            cp_async16(dst, srcb + (size_t)r * DIM * 2 + c16 * 16);
        }
        CP_COMMIT();
    };
    loadB(bs_base, 0);

    // per-thread ldmatrix address components
    uint32_t aoff[4]; int asw[4];
#pragma unroll
    for (int mf = 0; mf < 4; mf++) {
        int arow = warpM * 64 + mf * 16 + (lane & 15);
        aoff[mf] = as_base + arow * 512;
        asw[mf]  = arow & 7;
    }
    const int ahalf = (lane >> 4) & 1;
    uint32_t boff[4]; int bsw[4];
#pragma unroll
    for (int p = 0; p < 4; p++) {
        int code = warpN * 64 + p * 16 + ((lane >> 4) & 1) * 8 + (lane & 7);
        boff[p] = code * 128;
        bsw[p]  = code & 7;
    }
    const int bku = (lane >> 3) & 1;

    float acc[4][8][4];
#pragma unroll
    for (int i = 0; i < 4; i++)
#pragma unroll
        for (int j = 0; j < 8; j++)
#pragma unroll
            for (int k = 0; k < 4; k++) acc[i][j][k] = 0.0f;

    for (int j = 0; j < 4 * NTILES; j++) {
        if (j + 1 < 4 * NTILES) {
            loadB(bs_base + ((j + 1) & 1) * BS_BYTES, j + 1);
            asm volatile("cp.async.wait_group 1;" ::: "memory");
        } else {
            asm volatile("cp.async.wait_group 0;" ::: "memory");
        }
        __syncthreads();

        const uint32_t buf = bs_base + (j & 1) * BS_BYTES;
        const int c = j & 3;
#pragma unroll
        for (int k16 = 0; k16 < 4; k16++) {
            const int kk = k16 * 16;
            uint32_t b[8][2];
#pragma unroll
            for (int p = 0; p < 4; p++) {
                uint32_t addr = buf + boff[p] + ((((kk >> 3) + bku) ^ bsw[p]) << 4);
                ldm_x4(b[2 * p][0], b[2 * p][1], b[2 * p + 1][0], b[2 * p + 1][1], addr);
            }
            uint32_t a[4][4];
            const int uab = c * 8 + k16 * 2 + ahalf;
#pragma unroll
            for (int mf = 0; mf < 4; mf++) {
                uint32_t addr = aoff[mf] + ((uab ^ asw[mf]) << 4);
                ldm_x4(a[mf][0], a[mf][1], a[mf][2], a[mf][3], addr);
            }
#pragma unroll
            for (int mf = 0; mf < 4; mf++)
#pragma unroll
                for (int nf = 0; nf < 8; nf++)
                    mma16816(acc[mf][nf], a[mf], b[nf][0], b[nf][1]);
        }

        if (c == 3) {
            const int nt = j >> 2;
            // phase 1: per-row max via fmax tree + quad shuffle + 1 atomic
#pragma unroll
            for (int mf = 0; mf < 4; mf++)
#pragma unroll
                for (int h = 0; h < 2; h++) {
                    int r = warpM * 64 + mf * 16 + h * 8 + (lane >> 2);
                    float m = fmaxf(acc[mf][0][2 * h], acc[mf][0][2 * h + 1]);
#pragma unroll
                    for (int nf = 1; nf < 8; nf++)
                        m = fmaxf(m, fmaxf(acc[mf][nf][2 * h], acc[mf][nf][2 * h + 1]));
                    m = fmaxf(m, __shfl_xor_sync(0xFFFFFFFFu, m, 1));
                    m = fmaxf(m, __shfl_xor_sync(0xFFFFFFFFu, m, 2));
                    if ((lane & 3) == 0) atomicMax(&rowmax[r], fenc(m));
                }
            __syncthreads();
            // phase 2: append candidates within margin of running max
#pragma unroll
            for (int mf = 0; mf < 4; mf++)
#pragma unroll
                for (int h = 0; h < 2; h++) {
                    int r = warpM * 64 + mf * 16 + h * 8 + (lane >> 2);
                    float thr = fdec(rowmax[r]) - MARGIN;
#pragma unroll
                    for (int nf = 0; nf < 8; nf++) {
                        int cb0 = nt * 128 + warpN * 64 + nf * 8 + (lane & 3) * 2;
                        float va = acc[mf][nf][2 * h], vb = acc[mf][nf][2 * h + 1];
                        if (va >= thr) {
                            int p = atomicAdd(&cnt[r], 1);
                            if (p < MAX_CAND) cand[r * MAX_CAND + p] = cb0;
                        }
                        if (vb >= thr) {
                            int p = atomicAdd(&cnt[r], 1);
                            if (p < MAX_CAND) cand[r * MAX_CAND + p] = cb0 + 1;
                        }
                    }
                }
#pragma unroll
            for (int i = 0; i < 4; i++)
#pragma unroll
                for (int jj = 0; jj < 8; jj++)
#pragma unroll
                    for (int k = 0; k < 4; k++) acc[i][jj][k] = 0.0f;
        }
        __syncthreads();
    }

    // flush candidate lists (128 threads = 128 rows)
    {
        int row = m0 + tid;
        int c = cnt[tid];
        g_ccnt[row] = c;
        int n = c < MAX_CAND ? c : MAX_CAND;
        for (int i = 0; i < n; i++) g_cand[row * MAX_CAND + i] = cand[tid * MAX_CAND + i];
        if (c > MAX_CAND) {
            int p = atomicAdd(&g_ambig_n, 1);
            if (p < MAX_AMBIG) g_ambig[p] = row;
        }
    }
}

// ------------------------- K2b: exact fp32 rescore + histogram -------------
__global__ void vq_rescore(const float* __restrict__ x) {
    const int lane = threadIdx.x & 31;
    const int wid  = threadIdx.x >> 5;
#pragma unroll
    for (int i = 0; i < 4; i++) {
        int row = (blockIdx.x * 8 + wid) * 4 + i;
        int c = g_ccnt[row];
        if (c > MAX_CAND) continue;           // fallback path owns this row
        float xv[8];
#pragma unroll
        for (int jj = 0; jj < 8; jj++) xv[jj] = x[(size_t)row * DIM + lane + jj * 32];
        float bv = -3.0e38f; int bi = 0x7FFFFFFF;
        for (int k = 0; k < c; k++) {
            int code = g_cand[row * MAX_CAND + k];
            const float* cr = g_cbn + (size_t)code * DIM;
            float s = 0.0f;
#pragma unroll
            for (int jj = 0; jj < 8; jj++) s = fmaf(xv[jj], cr[lane + jj * 32], s);
#pragma unroll
            for (int m = 16; m > 0; m >>= 1) s += __shfl_xor_sync(0xFFFFFFFFu, s, m);
            if (better(s, code, bv, bi)) { bv = s; bi = code; }
        }
        if (lane == 0) {
            g_idx[row] = bi;
            atomicAdd(&g_counts[bi], 1);
        }
    }
}

// ------------------------- K2c/K2d: fallback full scan (overflow rows) -----
__global__ void vq_rescue_partial(const float* __restrict__ x) {
    const int slice = blockIdx.x >> 2;
    const int rmod  = blockIdx.x & 3;
    int n = g_ambig_n; if (n > MAX_AMBIG) n = MAX_AMBIG;
    const int code_l  = threadIdx.x & 63;
    const int quarter = threadIdx.x >> 6;
    const int code    = slice * 64 + code_l;

    __shared__ float xs[256];
    __shared__ float part[4][64];
    __shared__ float swv[2];
    __shared__ int   swi[2];

    for (int fi = rmod; fi < n; fi += 4) {
        int row = g_ambig[fi];
        xs[threadIdx.x] = x[(size_t)row * DIM + threadIdx.x];
        __syncthreads();
        const float* cbr = g_cbn + (size_t)code * DIM + quarter * 64;
        float s = 0.0f;
#pragma unroll 8
        for (int d = 0; d < 64; d++) s = fmaf(xs[quarter * 64 + d], cbr[d], s);
        part[quarter][code_l] = s;
        __syncthreads();
        if (threadIdx.x < 64) {
            float tot = (part[0][code_l] + part[1][code_l]) +
                        (part[2][code_l] + part[3][code_l]);
            float bv = tot; int bi = code;
#pragma unroll
            for (int m = 16; m > 0; m >>= 1) {
                float ov = __shfl_xor_sync(0xFFFFFFFFu, bv, m);
                int   oi = __shfl_xor_sync(0xFFFFFFFFu, bi, m);
                if (better(ov, oi, bv, bi)) { bv = ov; bi = oi; }
            }
            if ((threadIdx.x & 31) == 0) { swv[threadIdx.x >> 5] = bv; swi[threadIdx.x >> 5] = bi; }
        }
        __syncthreads();
        if (threadIdx.x == 0) {
            float bv = swv[0]; int bi = swi[0];
            if (better(swv[1], swi[1], bv, bi)) { bv = swv[1]; bi = swi[1]; }
            g_resc_v[fi * 64 + slice] = bv;
            g_resc_i[fi * 64 + slice] = bi;
        }
        __syncthreads();
    }
}

__global__ void vq_rescue_merge() {
    int fi = blockIdx.x * 256 + threadIdx.x;
    int n = g_ambig_n; if (n > MAX_AMBIG) n = MAX_AMBIG;
    if (fi < n) {
        float bv = g_resc_v[fi * 64]; int bi = g_resc_i[fi * 64];
        for (int s = 1; s < 64; s++) {
            float ov = g_resc_v[fi * 64 + s]; int oi = g_resc_i[fi * 64 + s];
            if (better(ov, oi, bv, bi)) { bv = ov; bi = oi; }
        }
        g_idx[g_ambig[fi]] = bi;
        atomicAdd(&g_counts[bi], 1);
    }
}

// ------------------------- K3: gather + z_q + loss -------------------------
__global__ void vq_gather_loss(const float* __restrict__ x,
                               const float* __restrict__ cb,
                               float* __restrict__ out) {
    const int m0 = blockIdx.x * 64;
    const int t  = threadIdx.x;
    const int col = (t & 63) * 4;
    float facc = 0.0f;
#pragma unroll 4
    for (int it = 0; it < 16; it++) {
        int row = m0 + it * 4 + (t >> 6);
        int code = g_idx[row];
        float4 xv = *(const float4*)(x + (size_t)row * DIM + col);
        float4 cv = *(const float4*)(cb + (size_t)code * DIM + col);
        float4 o;
        o.x = xv.x + (cv.x - xv.x);
        o.y = xv.y + (cv.y - xv.y);
        o.z = xv.z + (cv.z - xv.z);
        o.w = xv.w + (cv.w - xv.w);
        *(float4*)(out + (size_t)row * DIM + col) = o;
        float d0 = xv.x - cv.x, d1 = xv.y - cv.y, d2 = xv.z - cv.z, d3 = xv.w - cv.w;
        facc += d0 * d0 + d1 * d1 + d2 * d2 + d3 * d3;
    }
    __shared__ double sred[256];
    sred[t] = (double)facc;
    __syncthreads();
    for (int s = 128; s > 0; s >>= 1) {
        if (t < s) sred[t] += sred[t + s];
        __syncthreads();
    }
    if (t == 0) g_partials[blockIdx.x] = sred[0];
}

// ------------------------- K4: finalize ------------------------------------
__global__ void vq_finalize(float* __restrict__ out, int out_size) {
    const int t = threadIdx.x;
    __shared__ double sred[256];
    sred[t] = g_partials[t] + g_partials[t + 256] + g_partials[t + 512] + g_partials[t + 768];
    __syncthreads();
    for (int s = 128; s > 0; s >>= 1) {
        if (t < s) sred[t] += sred[t + s];
        __syncthreads();
    }
    double q = sred[0] / (double)ZQ_ELEMS;
    __syncthreads();

    double h = 0.0;
    for (int k = t; k < K_CODES; k += 256) {
        int c = g_counts[k];
        if (c > 0) {
            double p = (double)c / (double)B_ROWS;
            h -= p * log(p);
        }
    }
    sred[t] = h;
    __syncthreads();
    for (int s = 128; s > 0; s >>= 1) {
        if (t < s) sred[t] += sred[t + s];
        __syncthreads();
    }
    double H = sred[0];

    if (t == 0 && out_size >= SCAL_OFF + 5) {
        out[SCAL_OFF + 0] = (float)(1.25 * q - 0.1 * H);
        out[SCAL_OFF + 1] = (float)q;
        out[SCAL_OFF + 2] = (float)q;
        out[SCAL_OFF + 3] = (float)(-H);
        out[SCAL_OFF + 4] = (float)H;
    }
    if (out_size >= IDX_OFF + B_ROWS) {
        for (int i = t; i < B_ROWS; i += 256)
            out[IDX_OFF + i] = (float)g_idx[i];
    }
}

// ------------------------- launch ------------------------------------------
extern "C" void kernel_launch(void* const* d_in, const int* in_sizes, int n_in,
                              void* d_out, int out_size) {
    const float* x  = (const float*)d_in[0];
    const float* cb = (const float*)d_in[1];
    if (n_in >= 2 && in_sizes[0] == K_CODES * DIM && in_sizes[1] == B_ROWS * DIM) {
        x  = (const float*)d_in[1];
        cb = (const float*)d_in[0];
    }
    float* out = (float*)d_out;

    static bool attr_set = false;
    if (!attr_set) {
        cudaFuncSetAttribute(vq_mma_argmax,
                             cudaFuncAttributeMaxDynamicSharedMemorySize,
                             (int)SMEM_TOT);
        attr_set = true;
    }

    vq_zero_stats<<<16, 256>>>();
    vq_prep_x<<<ZQ_ELEMS / 4 / 256, 256>>>(x);
    vq_prep_cb<<<K_CODES, 256>>>(cb);
    vq_mma_argmax<<<B_ROWS / 128, 128, SMEM_TOT>>>();
    vq_rescore<<<B_ROWS / 32, 256>>>(x);
    vq_rescue_partial<<<256, 256>>>(x);
    vq_rescue_merge<<<MAX_AMBIG / 256, 256>>>();
    vq_gather_loss<<<B_ROWS / 64, 256>>>(x, cb, out);
    vq_finalize<<<1, 256>>>(out, out_size);
}